// round 2
// baseline (speedup 1.0000x reference)
#include <cuda_runtime.h>
#include <cuda_bf16.h>
#include <cub/cub.cuh>

#define BN   4
#define CIN  3
#define CO   64
#define HH   512
#define WW   512
#define SS   (HH*WW)        /* 262144 = 2^18 */
#define NC   (BN*CO)        /* 256 */
#define HR   448
#define MM   (HR*HR)        /* 200704 */
#define NCS  (NC*SS)        /* 67108864 = 2^26 */
#define NCM  (NC*MM)        /* 51380224 */

// ---------------- static device scratch (no runtime allocation) ----------------
__device__ unsigned long long g_src_keys[NCS];
__device__ unsigned long long g_src_sorted[NCS];
__device__ unsigned long long g_ref_keys[NCM];
__device__ unsigned long long g_ref_sorted[NCM];
__device__ char   g_cub_temp[1073741824];  // 1 GB temp for CUB radix sort
__device__ double g_accum[3];              // content, style, hist sums
__device__ float  g_gram[BN*CO*CO];

// ---------------- helpers ----------------
__device__ __forceinline__ unsigned int f2s(float x) {
    unsigned int u = __float_as_uint(x);
    return (u & 0x80000000u) ? ~u : (u | 0x80000000u);
}
__device__ __forceinline__ float s2f(unsigned int k) {
    unsigned int u = (k & 0x80000000u) ? (k ^ 0x80000000u) : ~k;
    return __uint_as_float(u);
}

__device__ __forceinline__ void block_add(double v, double* target) {
    __shared__ double sh[8];
    int tid  = threadIdx.x + threadIdx.y * blockDim.x;
    int lane = tid & 31, wid = tid >> 5;
    int nwarps = (blockDim.x * blockDim.y + 31) >> 5;
    #pragma unroll
    for (int o = 16; o > 0; o >>= 1) v += __shfl_down_sync(0xffffffffu, v, o);
    if (lane == 0) sh[wid] = v;
    __syncthreads();
    if (wid == 0) {
        v = (lane < nwarps) ? sh[lane] : 0.0;
        #pragma unroll
        for (int o = 4; o > 0; o >>= 1) v += __shfl_down_sync(0xffffffffu, v, o);
        if (lane == 0) atomicAdd(target, v);
    }
}

// ---------------- init ----------------
__global__ void init_kernel() {
    int i = blockIdx.x * 256 + threadIdx.x;
    if (i < 3) g_accum[i] = 0.0;
    if (i < BN*CO*CO) g_gram[i] = 0.0f;
}

// ---------------- conv + bias + relu + content-loss (fused) ----------------
__global__ void conv_kernel(const float* __restrict__ img, const float* __restrict__ w,
                            const float* __restrict__ b,   const float* __restrict__ ct,
                            float* __restrict__ out) {
    __shared__ float sin[3][10][34];
    __shared__ float sw[27][64];
    __shared__ float sb[64];
    const int n  = blockIdx.z;
    const int x0 = blockIdx.x * 32;
    const int y0 = blockIdx.y * 8;
    const int tid = threadIdx.y * 32 + threadIdx.x;

    for (int i = tid; i < 1728; i += 256) { int co = i / 27, tap = i % 27; sw[tap][co] = w[i]; }
    if (tid < 64) sb[tid] = b[tid];

    const float mean[3] = {0.485f, 0.456f, 0.406f};
    const float istd[3] = {1.f/0.229f, 1.f/0.224f, 1.f/0.225f};
    #pragma unroll
    for (int c = 0; c < 3; c++) {
        for (int i = tid; i < 340; i += 256) {
            int r = i / 34, cc = i % 34;
            int gy = y0 + r - 1, gx = x0 + cc - 1;
            float v = 0.f;
            if (gy >= 0 && gy < HH && gx >= 0 && gx < WW)
                v = (img[((n*3 + c)*HH + gy)*WW + gx] - mean[c]) * istd[c];
            sin[c][r][cc] = v;
        }
    }
    __syncthreads();

    const int px = threadIdx.x, py = threadIdx.y;
    float v[27];
    #pragma unroll
    for (int c = 0; c < 3; c++)
        #pragma unroll
        for (int ky = 0; ky < 3; ky++)
            #pragma unroll
            for (int kx = 0; kx < 3; kx++)
                v[c*9 + ky*3 + kx] = sin[c][py + ky][px + kx];

    const int y = y0 + py, x = x0 + px;
    double dsum = 0.0;
    #pragma unroll
    for (int cb = 0; cb < 64; cb += 16) {
        float acc[16];
        #pragma unroll
        for (int j = 0; j < 16; j++) acc[j] = sb[cb + j];
        #pragma unroll
        for (int t2 = 0; t2 < 27; t2++) {
            float vv = v[t2];
            #pragma unroll
            for (int j = 0; j < 16; j++) acc[j] = fmaf(vv, sw[t2][cb + j], acc[j]);
        }
        #pragma unroll
        for (int j = 0; j < 16; j++) {
            float f = acc[j] > 0.f ? acc[j] : 0.f;
            unsigned int oi = (unsigned int)(n*64 + cb + j) * SS + (unsigned int)y * WW + x;
            out[oi] = f;
            float d = f - ct[oi];
            dsum += (double)d * (double)d;
        }
    }
    block_add(dsum, &g_accum[0]);
}

// ---------------- key packing (chan<<32 | sortable_f32) ----------------
__global__ void pack_keys(const float4* __restrict__ vals, unsigned long long* __restrict__ keys,
                          unsigned int n4, unsigned int segsize) {
    unsigned int t = blockIdx.x * 256 + threadIdx.x;
    if (t >= n4) return;
    float4 v = vals[t];
    unsigned int base = t * 4u;
    unsigned long long ch = (unsigned long long)(base / segsize) << 32;
    keys[base + 0] = ch | f2s(v.x);
    keys[base + 1] = ch | f2s(v.y);
    keys[base + 2] = ch | f2s(v.z);
    keys[base + 3] = ch | f2s(v.w);
}

// ---------------- gram: per-batch F F^T, smem-tiled ----------------
#define GK 4096
#define GC 128
__global__ void gram_kernel(const float* __restrict__ feat) {
    __shared__ float tile[GC][68];
    const int n = blockIdx.y;
    const int base = blockIdx.x * GK;
    const int tid = threadIdx.x;
    const int r0 = (tid / 16) * 4, c0 = (tid % 16) * 4;
    float acc[4][4] = {};
    for (int cb = 0; cb < GK; cb += GC) {
        __syncthreads();
        #pragma unroll
        for (int it = 0; it < 32; it++) {
            int li = it * 256 + tid;
            int ch = li >> 7, k = li & 127;
            tile[k][ch] = feat[(unsigned int)(n*64 + ch) * SS + base + cb + k];
        }
        __syncthreads();
        #pragma unroll 4
        for (int k = 0; k < GC; k++) {
            float4 a  = *(const float4*)&tile[k][r0];
            float4 bq = *(const float4*)&tile[k][c0];
            acc[0][0] = fmaf(a.x, bq.x, acc[0][0]); acc[0][1] = fmaf(a.x, bq.y, acc[0][1]);
            acc[0][2] = fmaf(a.x, bq.z, acc[0][2]); acc[0][3] = fmaf(a.x, bq.w, acc[0][3]);
            acc[1][0] = fmaf(a.y, bq.x, acc[1][0]); acc[1][1] = fmaf(a.y, bq.y, acc[1][1]);
            acc[1][2] = fmaf(a.y, bq.z, acc[1][2]); acc[1][3] = fmaf(a.y, bq.w, acc[1][3]);
            acc[2][0] = fmaf(a.z, bq.x, acc[2][0]); acc[2][1] = fmaf(a.z, bq.y, acc[2][1]);
            acc[2][2] = fmaf(a.z, bq.z, acc[2][2]); acc[2][3] = fmaf(a.z, bq.w, acc[2][3]);
            acc[3][0] = fmaf(a.w, bq.x, acc[3][0]); acc[3][1] = fmaf(a.w, bq.y, acc[3][1]);
            acc[3][2] = fmaf(a.w, bq.z, acc[3][2]); acc[3][3] = fmaf(a.w, bq.w, acc[3][3]);
        }
    }
    #pragma unroll
    for (int i = 0; i < 4; i++)
        #pragma unroll
        for (int j = 0; j < 4; j++)
            atomicAdd(&g_gram[n*4096 + (r0 + i)*64 + c0 + j], acc[i][j]);
}

// ---------------- style loss ----------------
__global__ void style_kernel(const float* __restrict__ tgt) {
    int i = blockIdx.x * 256 + threadIdx.x;
    double d = 0.0;
    if (i < BN*CO*CO) {
        float g = g_gram[i] * (1.0f / ((float)CO * HH * WW));
        float df = g - tgt[i];
        d = (double)df * (double)df;
    }
    block_add(d, &g_accum[1]);
}

// ---------------- hist loss: sum (sorted_src[i] - lerp(sorted_ref, pos_i))^2 ----------------
__global__ void hist_kernel() {
    unsigned int b0 = blockIdx.x * 2048u;
    const float step = (float)(MM - 1) / (float)(SS - 1);
    double d = 0.0;
    #pragma unroll
    for (int it = 0; it < 8; it++) {
        unsigned int idx = b0 + it * 256 + threadIdx.x;
        unsigned int c = idx >> 18;           // / SS
        unsigned int i = idx & (SS - 1);
        float sv  = s2f((unsigned int)(g_src_sorted[idx] & 0xffffffffu));
        float pos = step * (float)i;
        int lo = (int)floorf(pos);
        int hi = (int)ceilf(pos);
        if (lo > MM - 1) lo = MM - 1;
        if (hi > MM - 1) hi = MM - 1;
        float w   = pos - (float)lo;
        float rlo = s2f((unsigned int)(g_ref_sorted[c * MM + lo] & 0xffffffffu));
        float rhi = s2f((unsigned int)(g_ref_sorted[c * MM + hi] & 0xffffffffu));
        float r   = rlo * (1.0f - w) + rhi * w;
        float df  = sv - r;
        d += (double)df * (double)df;
    }
    block_add(d, &g_accum[2]);
}

// ---------------- finalize ----------------
__global__ void finalize_kernel(float* __restrict__ out) {
    if (threadIdx.x == 0) {
        out[NCS + 0] = (float)(g_accum[0] / (double)NCS);
        out[NCS + 1] = (float)(g_accum[1] / (double)(BN*CO*CO));
        out[NCS + 2] = (float)(g_accum[2] / (double)NCS);
    }
}

// ---------------- launch ----------------
extern "C" void kernel_launch(void* const* d_in, const int* in_sizes, int n_in,
                              void* d_out, int out_size) {
    const float* img  = (const float*)d_in[0];
    const float* w    = (const float*)d_in[1];
    const float* b    = (const float*)d_in[2];
    const float* ct   = (const float*)d_in[3];
    const float* stg  = (const float*)d_in[4];
    const float* hist = (const float*)d_in[5];
    float* out = (float*)d_out;

    void *p_src, *p_src_s, *p_ref, *p_ref_s, *p_temp;
    cudaGetSymbolAddress(&p_src,   g_src_keys);
    cudaGetSymbolAddress(&p_src_s, g_src_sorted);
    cudaGetSymbolAddress(&p_ref,   g_ref_keys);
    cudaGetSymbolAddress(&p_ref_s, g_ref_sorted);
    cudaGetSymbolAddress(&p_temp,  g_cub_temp);

    init_kernel<<<64, 256>>>();

    dim3 cgrid(WW/32, HH/8, BN), cblk(32, 8);
    conv_kernel<<<cgrid, cblk>>>(img, w, b, ct, out);

    // feat keys + sort (bits [0,40): 32 value bits + 8 channel bits)
    pack_keys<<<(NCS/4 + 255)/256, 256>>>((const float4*)out, (unsigned long long*)p_src,
                                          NCS/4, (unsigned int)SS);
    {
        size_t tb = 0;
        cub::DeviceRadixSort::SortKeys(nullptr, tb,
            (const unsigned long long*)p_src, (unsigned long long*)p_src_s,
            (int)NCS, 0, 40, (cudaStream_t)0);
        cub::DeviceRadixSort::SortKeys(p_temp, tb,
            (const unsigned long long*)p_src, (unsigned long long*)p_src_s,
            (int)NCS, 0, 40, (cudaStream_t)0);
    }

    gram_kernel<<<dim3(SS/GK, BN), 256>>>(out);
    style_kernel<<<(BN*CO*CO + 255)/256, 256>>>(stg);

    // hist_target keys + sort
    pack_keys<<<(NCM/4 + 255)/256, 256>>>((const float4*)hist, (unsigned long long*)p_ref,
                                          NCM/4, (unsigned int)MM);
    {
        size_t tb = 0;
        cub::DeviceRadixSort::SortKeys(nullptr, tb,
            (const unsigned long long*)p_ref, (unsigned long long*)p_ref_s,
            (int)NCM, 0, 40, (cudaStream_t)0);
        cub::DeviceRadixSort::SortKeys(p_temp, tb,
            (const unsigned long long*)p_ref, (unsigned long long*)p_ref_s,
            (int)NCM, 0, 40, (cudaStream_t)0);
    }

    hist_kernel<<<NCS/2048, 256>>>();
    finalize_kernel<<<1, 32>>>(out);
    (void)in_sizes; (void)n_in; (void)out_size;
}

// round 3
// speedup vs baseline: 1.9789x; 1.9789x over previous
#include <cuda_runtime.h>
#include <cuda_bf16.h>
#include <cub/cub.cuh>

#define BN   4
#define CIN  3
#define CO   64
#define HH   512
#define WW   512
#define SS   (HH*WW)        /* 262144 = 2^18 */
#define NC   (BN*CO)        /* 256 */
#define HR   448
#define MM   (HR*HR)        /* 200704 */
#define NCS  (NC*SS)        /* 67108864 */
#define NCM  (NC*MM)        /* 51380224 */

// ---------------- static device scratch (no runtime allocation) ----------------
__device__ unsigned int g_src_keys[NCS];
__device__ unsigned int g_src_sorted[NCS];
__device__ unsigned int g_ref_keys[NCM];
__device__ unsigned int g_ref_sorted[NCM];
__device__ char   g_cub_temp[805306368];   // 768 MB temp for CUB radix sort
__device__ double g_accum[3];              // content, style, hist sums
__device__ float  g_gram[BN*CO*CO];

// ---------------- helpers ----------------
__device__ __forceinline__ unsigned int f2s(float x) {
    unsigned int u = __float_as_uint(x);
    return (u & 0x80000000u) ? ~u : (u | 0x80000000u);
}
__device__ __forceinline__ float s2f(unsigned int k) {
    unsigned int u = (k & 0x80000000u) ? (k ^ 0x80000000u) : ~k;
    return __uint_as_float(u);
}
// reconstruct float from 24-bit truncated sortable (midpoint of truncation bucket)
__device__ __forceinline__ float key2f(unsigned int k24) {
    return s2f(((k24 & 0xFFFFFFu) << 8) | 0x80u);
}

__device__ __forceinline__ void block_add(double v, double* target) {
    __shared__ double sh[8];
    int tid  = threadIdx.x + threadIdx.y * blockDim.x;
    int lane = tid & 31, wid = tid >> 5;
    int nwarps = (blockDim.x * blockDim.y + 31) >> 5;
    #pragma unroll
    for (int o = 16; o > 0; o >>= 1) v += __shfl_down_sync(0xffffffffu, v, o);
    if (lane == 0) sh[wid] = v;
    __syncthreads();
    if (wid == 0) {
        v = (lane < nwarps) ? sh[lane] : 0.0;
        #pragma unroll
        for (int o = 4; o > 0; o >>= 1) v += __shfl_down_sync(0xffffffffu, v, o);
        if (lane == 0) atomicAdd(target, v);
    }
}

// ---------------- init ----------------
__global__ void init_kernel() {
    int i = blockIdx.x * 256 + threadIdx.x;
    if (i < 3) g_accum[i] = 0.0;
    if (i < BN*CO*CO) g_gram[i] = 0.0f;
}

// ------ conv + bias + relu + content-loss + sort-key emission (fused) ------
__global__ void conv_kernel(const float* __restrict__ img, const float* __restrict__ w,
                            const float* __restrict__ b,   const float* __restrict__ ct,
                            float* __restrict__ out,       unsigned int* __restrict__ keys) {
    __shared__ float sin[3][10][34];
    __shared__ float sw[27][64];
    __shared__ float sb[64];
    const int n  = blockIdx.z;
    const int x0 = blockIdx.x * 32;
    const int y0 = blockIdx.y * 8;
    const int tid = threadIdx.y * 32 + threadIdx.x;

    for (int i = tid; i < 1728; i += 256) { int co = i / 27, tap = i % 27; sw[tap][co] = w[i]; }
    if (tid < 64) sb[tid] = b[tid];

    const float mean[3] = {0.485f, 0.456f, 0.406f};
    const float istd[3] = {1.f/0.229f, 1.f/0.224f, 1.f/0.225f};
    #pragma unroll
    for (int c = 0; c < 3; c++) {
        for (int i = tid; i < 340; i += 256) {
            int r = i / 34, cc = i % 34;
            int gy = y0 + r - 1, gx = x0 + cc - 1;
            float v = 0.f;
            if (gy >= 0 && gy < HH && gx >= 0 && gx < WW)
                v = (img[((n*3 + c)*HH + gy)*WW + gx] - mean[c]) * istd[c];
            sin[c][r][cc] = v;
        }
    }
    __syncthreads();

    const int px = threadIdx.x, py = threadIdx.y;
    float v[27];
    #pragma unroll
    for (int c = 0; c < 3; c++)
        #pragma unroll
        for (int ky = 0; ky < 3; ky++)
            #pragma unroll
            for (int kx = 0; kx < 3; kx++)
                v[c*9 + ky*3 + kx] = sin[c][py + ky][px + kx];

    const int y = y0 + py, x = x0 + px;
    double dsum = 0.0;
    #pragma unroll
    for (int cb = 0; cb < 64; cb += 16) {
        float acc[16];
        #pragma unroll
        for (int j = 0; j < 16; j++) acc[j] = sb[cb + j];
        #pragma unroll
        for (int t2 = 0; t2 < 27; t2++) {
            float vv = v[t2];
            #pragma unroll
            for (int j = 0; j < 16; j++) acc[j] = fmaf(vv, sw[t2][cb + j], acc[j]);
        }
        #pragma unroll
        for (int j = 0; j < 16; j++) {
            float f = acc[j] > 0.f ? acc[j] : 0.f;
            unsigned int ch = (unsigned int)(n*64 + cb + j);
            unsigned int oi = ch * SS + (unsigned int)y * WW + x;
            out[oi] = f;
            keys[oi] = (ch << 24) | (f2s(f) >> 8);
            float d = f - ct[oi];
            dsum += (double)d * (double)d;
        }
    }
    block_add(dsum, &g_accum[0]);
}

// ---------------- ref key packing (chan<<24 | sortable>>8) ----------------
__global__ void pack_keys(const float4* __restrict__ vals, unsigned int* __restrict__ keys,
                          unsigned int n4, unsigned int segsize) {
    unsigned int t = blockIdx.x * 256 + threadIdx.x;
    if (t >= n4) return;
    float4 v = vals[t];
    unsigned int base = t * 4u;
    unsigned int ch = (base / segsize) << 24;
    uint4 o;
    o.x = ch | (f2s(v.x) >> 8);
    o.y = ch | (f2s(v.y) >> 8);
    o.z = ch | (f2s(v.z) >> 8);
    o.w = ch | (f2s(v.w) >> 8);
    *(uint4*)&keys[base] = o;
}

// ---------------- gram: per-batch F F^T, smem-tiled ----------------
#define GK 4096
#define GC 128
__global__ void gram_kernel(const float* __restrict__ feat) {
    __shared__ float tile[GC][68];
    const int n = blockIdx.y;
    const int base = blockIdx.x * GK;
    const int tid = threadIdx.x;
    const int r0 = (tid / 16) * 4, c0 = (tid % 16) * 4;
    float acc[4][4] = {};
    for (int cb = 0; cb < GK; cb += GC) {
        __syncthreads();
        #pragma unroll
        for (int it = 0; it < 32; it++) {
            int li = it * 256 + tid;
            int ch = li >> 7, k = li & 127;
            tile[k][ch] = feat[(unsigned int)(n*64 + ch) * SS + base + cb + k];
        }
        __syncthreads();
        #pragma unroll 4
        for (int k = 0; k < GC; k++) {
            float4 a  = *(const float4*)&tile[k][r0];
            float4 bq = *(const float4*)&tile[k][c0];
            acc[0][0] = fmaf(a.x, bq.x, acc[0][0]); acc[0][1] = fmaf(a.x, bq.y, acc[0][1]);
            acc[0][2] = fmaf(a.x, bq.z, acc[0][2]); acc[0][3] = fmaf(a.x, bq.w, acc[0][3]);
            acc[1][0] = fmaf(a.y, bq.x, acc[1][0]); acc[1][1] = fmaf(a.y, bq.y, acc[1][1]);
            acc[1][2] = fmaf(a.y, bq.z, acc[1][2]); acc[1][3] = fmaf(a.y, bq.w, acc[1][3]);
            acc[2][0] = fmaf(a.z, bq.x, acc[2][0]); acc[2][1] = fmaf(a.z, bq.y, acc[2][1]);
            acc[2][2] = fmaf(a.z, bq.z, acc[2][2]); acc[2][3] = fmaf(a.z, bq.w, acc[2][3]);
            acc[3][0] = fmaf(a.w, bq.x, acc[3][0]); acc[3][1] = fmaf(a.w, bq.y, acc[3][1]);
            acc[3][2] = fmaf(a.w, bq.z, acc[3][2]); acc[3][3] = fmaf(a.w, bq.w, acc[3][3]);
        }
    }
    #pragma unroll
    for (int i = 0; i < 4; i++)
        #pragma unroll
        for (int j = 0; j < 4; j++)
            atomicAdd(&g_gram[n*4096 + (r0 + i)*64 + c0 + j], acc[i][j]);
}

// ---------------- style loss ----------------
__global__ void style_kernel(const float* __restrict__ tgt) {
    int i = blockIdx.x * 256 + threadIdx.x;
    double d = 0.0;
    if (i < BN*CO*CO) {
        float g = g_gram[i] * (1.0f / ((float)CO * HH * WW));
        float df = g - tgt[i];
        d = (double)df * (double)df;
    }
    block_add(d, &g_accum[1]);
}

// -------- hist loss: sum (sorted_src[i] - lerp(sorted_ref, pos_i))^2 --------
__global__ void hist_kernel() {
    unsigned int b0 = blockIdx.x * 2048u;
    const float step = (float)(MM - 1) / (float)(SS - 1);
    double d = 0.0;
    #pragma unroll
    for (int it = 0; it < 8; it++) {
        unsigned int idx = b0 + it * 256 + threadIdx.x;
        unsigned int c = idx >> 18;           // / SS
        unsigned int i = idx & (SS - 1);
        float sv  = key2f(g_src_sorted[idx]);
        float pos = step * (float)i;
        int lo = (int)floorf(pos);
        int hi = (int)ceilf(pos);
        if (lo > MM - 1) lo = MM - 1;
        if (hi > MM - 1) hi = MM - 1;
        float w   = pos - (float)lo;
        float rlo = key2f(g_ref_sorted[c * MM + lo]);
        float rhi = key2f(g_ref_sorted[c * MM + hi]);
        float r   = rlo * (1.0f - w) + rhi * w;
        float df  = sv - r;
        d += (double)df * (double)df;
    }
    block_add(d, &g_accum[2]);
}

// ---------------- finalize ----------------
__global__ void finalize_kernel(float* __restrict__ out) {
    if (threadIdx.x == 0) {
        out[NCS + 0] = (float)(g_accum[0] / (double)NCS);
        out[NCS + 1] = (float)(g_accum[1] / (double)(BN*CO*CO));
        out[NCS + 2] = (float)(g_accum[2] / (double)NCS);
    }
}

// ---------------- launch ----------------
extern "C" void kernel_launch(void* const* d_in, const int* in_sizes, int n_in,
                              void* d_out, int out_size) {
    const float* img  = (const float*)d_in[0];
    const float* w    = (const float*)d_in[1];
    const float* b    = (const float*)d_in[2];
    const float* ct   = (const float*)d_in[3];
    const float* stg  = (const float*)d_in[4];
    const float* hist = (const float*)d_in[5];
    float* out = (float*)d_out;

    void *p_src, *p_src_s, *p_ref, *p_ref_s, *p_temp;
    cudaGetSymbolAddress(&p_src,   g_src_keys);
    cudaGetSymbolAddress(&p_src_s, g_src_sorted);
    cudaGetSymbolAddress(&p_ref,   g_ref_keys);
    cudaGetSymbolAddress(&p_ref_s, g_ref_sorted);
    cudaGetSymbolAddress(&p_temp,  g_cub_temp);

    init_kernel<<<64, 256>>>();

    dim3 cgrid(WW/32, HH/8, BN), cblk(32, 8);
    conv_kernel<<<cgrid, cblk>>>(img, w, b, ct, out, (unsigned int*)p_src);

    // feat sort: 32-bit keys (8-bit channel | 24-bit truncated sortable value)
    {
        size_t tb = 0;
        cub::DeviceRadixSort::SortKeys(nullptr, tb,
            (const unsigned int*)p_src, (unsigned int*)p_src_s,
            (int)NCS, 0, 32, (cudaStream_t)0);
        cub::DeviceRadixSort::SortKeys(p_temp, tb,
            (const unsigned int*)p_src, (unsigned int*)p_src_s,
            (int)NCS, 0, 32, (cudaStream_t)0);
    }

    gram_kernel<<<dim3(SS/GK, BN), 256>>>(out);
    style_kernel<<<(BN*CO*CO + 255)/256, 256>>>(stg);

    // hist_target keys + sort
    pack_keys<<<(NCM/4 + 255)/256, 256>>>((const float4*)hist, (unsigned int*)p_ref,
                                          NCM/4, (unsigned int)MM);
    {
        size_t tb = 0;
        cub::DeviceRadixSort::SortKeys(nullptr, tb,
            (const unsigned int*)p_ref, (unsigned int*)p_ref_s,
            (int)NCM, 0, 32, (cudaStream_t)0);
        cub::DeviceRadixSort::SortKeys(p_temp, tb,
            (const unsigned int*)p_ref, (unsigned int*)p_ref_s,
            (int)NCM, 0, 32, (cudaStream_t)0);
    }

    hist_kernel<<<NCS/2048, 256>>>();
    finalize_kernel<<<1, 32>>>(out);
    (void)in_sizes; (void)n_in; (void)out_size;
}